// round 4
// baseline (speedup 1.0000x reference)
#include <cuda_runtime.h>

// Problem constants (fixed-shape problem)
#define T_TOK 16384
#define H_DIM 4096
#define N_EXP 8
#define TOPK  2

// Global accumulators for aux loss: [0..8) = sum of probs per expert (P*T),
// [8..16) = top1 counts per expert (f*T). Zeroed via cudaMemsetAsync each launch.
__device__ float g_acc[16];

__global__ __launch_bounds__(512, 1)
void router_kernel(const float* __restrict__ hidden,
                   const float* __restrict__ gate_w,
                   float* __restrict__ out)
{
    extern __shared__ float sw[];     // 8 * 4096 floats = 128 KB, expert-major copy of gate_w
    __shared__ float sP[N_EXP];       // block-level prob sums
    __shared__ float sF[N_EXP];       // block-level top1 counts

    const int tid  = threadIdx.x;
    const int warp = tid >> 5;
    const int lane = tid & 31;

    if (tid < N_EXP)            sP[tid] = 0.0f;
    else if (tid < 2 * N_EXP)   sF[tid - N_EXP] = 0.0f;

    // Stage gate_w into shared memory (coalesced float4 copy)
    {
        const float4* gw4 = reinterpret_cast<const float4*>(gate_w);
        float4*       sw4 = reinterpret_cast<float4*>(sw);
        for (int i = tid; i < (N_EXP * H_DIM) / 4; i += 512)
            sw4[i] = gw4[i];
    }
    __syncthreads();

    // Token groups of 4, chunked per block for per-SM balance
    const int NG   = T_TOK / 4;                     // 4096 groups
    const int gpb  = (NG + gridDim.x - 1) / gridDim.x;
    const int gs   = blockIdx.x * gpb;
    int ge         = gs + gpb;
    if (ge > NG) ge = NG;

    const float4* h4  = reinterpret_cast<const float4*>(hidden);
    const float4* sw4 = reinterpret_cast<const float4*>(sw);

    float* out_w = out;                 // [T][2] routing weights
    float* out_e = out + 2 * T_TOK;     // [T][2] expert indices (as float)
    float* out_l = out + 4 * T_TOK;     // [T][8] router logits

    for (int g = gs + warp; g < ge; g += 16) {
        const int t0 = g * 4;

        float acc[4][N_EXP];
        #pragma unroll
        for (int t = 0; t < 4; ++t)
            #pragma unroll
            for (int e = 0; e < N_EXP; ++e)
                acc[t][e] = 0.0f;

        // hidden row of token t0+t, as float4: base index (t0+t)*1024 + lane
        const int hbase = t0 * (H_DIM / 4) + lane;

        #pragma unroll 2
        for (int it = 0; it < H_DIM / 128; ++it) {     // 32 iterations, 128 cols each
            float4 h[4];
            #pragma unroll
            for (int t = 0; t < 4; ++t)
                h[t] = h4[hbase + t * (H_DIM / 4) + it * 32];

            const int wbase = it * 32 + lane;           // float4 index within one expert row
            #pragma unroll
            for (int e = 0; e < N_EXP; ++e) {
                float4 w = sw4[e * (H_DIM / 4) + wbase];
                #pragma unroll
                for (int t = 0; t < 4; ++t) {
                    acc[t][e] = fmaf(h[t].x, w.x,
                                fmaf(h[t].y, w.y,
                                fmaf(h[t].z, w.z,
                                fmaf(h[t].w, w.w, acc[t][e]))));
                }
            }
        }

        // Butterfly reduction: every lane ends with the full dot products
        #pragma unroll
        for (int t = 0; t < 4; ++t)
            #pragma unroll
            for (int e = 0; e < N_EXP; ++e)
                #pragma unroll
                for (int off = 16; off > 0; off >>= 1)
                    acc[t][e] += __shfl_xor_sync(0xffffffffu, acc[t][e], off);

        // Lanes 0..3 each finish one token
        if (lane < 4) {
            const int token = t0 + lane;
            float l[N_EXP];
            #pragma unroll
            for (int e = 0; e < N_EXP; ++e) l[e] = acc[lane][e];

            float m = l[0];
            #pragma unroll
            for (int e = 1; e < N_EXP; ++e) m = fmaxf(m, l[e]);

            float p[N_EXP];
            float s = 0.0f;
            #pragma unroll
            for (int e = 0; e < N_EXP; ++e) { p[e] = expf(l[e] - m); s += p[e]; }
            const float inv = 1.0f / s;
            #pragma unroll
            for (int e = 0; e < N_EXP; ++e) p[e] *= inv;

            // top-2 by logit (same order as probs), ties -> lowest index
            int i1 = 0;
            #pragma unroll
            for (int e = 1; e < N_EXP; ++e) if (l[e] > l[i1]) i1 = e;
            int i2 = -1;
            #pragma unroll
            for (int e = 0; e < N_EXP; ++e) {
                if (e == i1) continue;
                if (i2 < 0 || l[e] > l[i2]) i2 = e;
            }

            const float w1 = p[i1], w2 = p[i2];
            const float si = 1.0f / (w1 + w2);
            out_w[token * 2 + 0] = w1 * si;
            out_w[token * 2 + 1] = w2 * si;
            out_e[token * 2 + 0] = (float)i1;
            out_e[token * 2 + 1] = (float)i2;

            float4 lo = make_float4(l[0], l[1], l[2], l[3]);
            float4 hi = make_float4(l[4], l[5], l[6], l[7]);
            reinterpret_cast<float4*>(out_l)[token * 2 + 0] = lo;
            reinterpret_cast<float4*>(out_l)[token * 2 + 1] = hi;

            #pragma unroll
            for (int e = 0; e < N_EXP; ++e) atomicAdd(&sP[e], p[e]);
            atomicAdd(&sF[i1], 1.0f);
        }
    }

    __syncthreads();
    if (tid < N_EXP)           atomicAdd(&g_acc[tid], sP[tid]);
    else if (tid < 2 * N_EXP)  atomicAdd(&g_acc[tid], sF[tid - N_EXP]);
}

__global__ void finalize_kernel(float* __restrict__ out)
{
    const float invT = 1.0f / (float)T_TOK;
    float s = 0.0f;
    #pragma unroll
    for (int e = 0; e < N_EXP; ++e) {
        float P = g_acc[e] * invT;
        float f = g_acc[N_EXP + e] * invT;
        s += f * P;
    }
    out[12 * T_TOK] = 0.01f * (float)N_EXP * s;
}

extern "C" void kernel_launch(void* const* d_in, const int* in_sizes, int n_in,
                              void* d_out, int out_size)
{
    const float* hidden = (const float*)d_in[0];
    const float* gate_w = (const float*)d_in[1];
    float* out = (float*)d_out;

    (void)in_sizes; (void)n_in; (void)out_size;

    const int smem = N_EXP * H_DIM * (int)sizeof(float);   // 131072 bytes
    cudaFuncSetAttribute(router_kernel,
                         cudaFuncAttributeMaxDynamicSharedMemorySize, smem);

    void* acc_ptr = nullptr;
    cudaGetSymbolAddress(&acc_ptr, g_acc);
    cudaMemsetAsync(acc_ptr, 0, 16 * sizeof(float), 0);

    router_kernel<<<148, 512, smem>>>(hidden, gate_w, out);
    finalize_kernel<<<1, 1>>>(out);
}

// round 5
// speedup vs baseline: 1.3505x; 1.3505x over previous
#include <cuda_runtime.h>
#include <cstdint>

// Problem constants (fixed-shape problem)
#define T_TOK 16384
#define H_DIM 4096
#define N_EXP 8
#define TOPK  2
#define NBLK  148
#define NWARP 16          // warps per block (512 threads)
#define GWARPS (NBLK * NWARP)

// Global accumulators for aux loss: [0..8) = sum of probs per expert,
// [8..16) = top1 counts. Zero-initialized at module load; the LAST block of
// each launch consumes them and resets to zero, so graph replays stay
// deterministic with no memset node and no second kernel.
__device__ float g_acc[16];
__device__ unsigned int g_ticket = 0;

__device__ __forceinline__ void ffma2(uint64_t& d, uint64_t a, uint64_t b) {
    // packed fp32x2 FMA: d.lo += a.lo*b.lo ; d.hi += a.hi*b.hi
    asm("fma.rn.f32x2 %0, %1, %2, %0;" : "+l"(d) : "l"(a), "l"(b));
}
__device__ __forceinline__ void ldg_cs_v2(uint64_t& a, uint64_t& b, const void* p) {
    asm("ld.global.cs.v2.u64 {%0,%1}, [%2];" : "=l"(a), "=l"(b) : "l"(p));
}
__device__ __forceinline__ void lds_v2(uint64_t& a, uint64_t& b, uint32_t addr) {
    asm("ld.shared.v2.u64 {%0,%1}, [%2];" : "=l"(a), "=l"(b) : "r"(addr));
}
__device__ __forceinline__ float unpack_sum(uint64_t v) {
    uint32_t lo, hi;
    asm("mov.b64 {%0,%1}, %2;" : "=r"(lo), "=r"(hi) : "l"(v));
    return __uint_as_float(lo) + __uint_as_float(hi);
}

__global__ __launch_bounds__(512, 1)
void router_kernel(const float* __restrict__ hidden,
                   const float* __restrict__ gate_w,
                   float* __restrict__ out)
{
    extern __shared__ float sw[];     // 8 * 4096 floats = 128 KB
    __shared__ float sP[N_EXP];
    __shared__ float sF[N_EXP];

    const int tid  = threadIdx.x;
    const int warp = tid >> 5;
    const int lane = tid & 31;

    if (tid < N_EXP)            sP[tid] = 0.0f;
    else if (tid < 2 * N_EXP)   sF[tid - N_EXP] = 0.0f;

    // Stage gate_w into shared memory (coalesced float4 copy)
    {
        const float4* gw4 = reinterpret_cast<const float4*>(gate_w);
        float4*       sw4 = reinterpret_cast<float4*>(sw);
        for (int i = tid; i < (N_EXP * H_DIM) / 4; i += 512)
            sw4[i] = gw4[i];
    }
    __syncthreads();

    const uint32_t sbase = (uint32_t)__cvta_generic_to_shared(sw);
    const char*    hbytes = reinterpret_cast<const char*>(hidden);

    float* out_w = out;                 // [T][2] routing weights
    float* out_e = out + 2 * T_TOK;     // [T][2] expert indices (as float)
    float* out_l = out + 4 * T_TOK;     // [T][8] router logits

    const int gw_id = blockIdx.x * NWARP + warp;

    for (int g = gw_id; g < T_TOK / 4; g += GWARPS) {
        const int t0 = g * 4;

        uint64_t acc[4][N_EXP];
        #pragma unroll
        for (int t = 0; t < 4; ++t)
            #pragma unroll
            for (int e = 0; e < N_EXP; ++e)
                acc[t][e] = 0ull;

        #pragma unroll 2
        for (int it = 0; it < H_DIM / 128; ++it) {          // 32 iterations
            const int c16 = (it * 32 + lane) * 16;          // byte offset in a row
            uint64_t ha[4], hb[4];
            #pragma unroll
            for (int t = 0; t < 4; ++t)
                ldg_cs_v2(ha[t], hb[t],
                          hbytes + (size_t)(t0 + t) * (H_DIM * 4) + c16);

            #pragma unroll
            for (int e = 0; e < N_EXP; ++e) {
                uint64_t wa, wb;
                lds_v2(wa, wb, sbase + e * (H_DIM * 4) + c16);
                #pragma unroll
                for (int t = 0; t < 4; ++t) {
                    ffma2(acc[t][e], ha[t], wa);
                    ffma2(acc[t][e], hb[t], wb);
                }
            }
        }

        // Collapse packed halves, then butterfly-reduce across the warp
        float af[4][N_EXP];
        #pragma unroll
        for (int t = 0; t < 4; ++t)
            #pragma unroll
            for (int e = 0; e < N_EXP; ++e) {
                float v = unpack_sum(acc[t][e]);
                #pragma unroll
                for (int off = 16; off > 0; off >>= 1)
                    v += __shfl_xor_sync(0xffffffffu, v, off);
                af[t][e] = v;
            }

        // Lanes 0..3 each finish one token
        if (lane < 4) {
            const int token = t0 + lane;
            float l[N_EXP];
            #pragma unroll
            for (int e = 0; e < N_EXP; ++e) l[e] = af[lane][e];

            float m = l[0];
            #pragma unroll
            for (int e = 1; e < N_EXP; ++e) m = fmaxf(m, l[e]);

            float p[N_EXP];
            float s = 0.0f;
            #pragma unroll
            for (int e = 0; e < N_EXP; ++e) { p[e] = expf(l[e] - m); s += p[e]; }
            const float inv = 1.0f / s;
            #pragma unroll
            for (int e = 0; e < N_EXP; ++e) p[e] *= inv;

            int i1 = 0;
            #pragma unroll
            for (int e = 1; e < N_EXP; ++e) if (l[e] > l[i1]) i1 = e;
            int i2 = -1;
            #pragma unroll
            for (int e = 0; e < N_EXP; ++e) {
                if (e == i1) continue;
                if (i2 < 0 || l[e] > l[i2]) i2 = e;
            }

            const float w1 = p[i1], w2 = p[i2];
            const float si = 1.0f / (w1 + w2);
            out_w[token * 2 + 0] = w1 * si;
            out_w[token * 2 + 1] = w2 * si;
            out_e[token * 2 + 0] = (float)i1;
            out_e[token * 2 + 1] = (float)i2;

            reinterpret_cast<float4*>(out_l)[token * 2 + 0] =
                make_float4(l[0], l[1], l[2], l[3]);
            reinterpret_cast<float4*>(out_l)[token * 2 + 1] =
                make_float4(l[4], l[5], l[6], l[7]);

            #pragma unroll
            for (int e = 0; e < N_EXP; ++e) atomicAdd(&sP[e], p[e]);
            atomicAdd(&sF[i1], 1.0f);
        }
    }

    __syncthreads();
    if (tid < N_EXP)           atomicAdd(&g_acc[tid], sP[tid]);
    else if (tid < 2 * N_EXP)  atomicAdd(&g_acc[tid], sF[tid - N_EXP]);
    __syncthreads();

    // Last-block finalize (threadFenceReduction pattern): compute aux loss,
    // then reset the global accumulators for the next graph replay.
    if (tid == 0) {
        __threadfence();
        unsigned int ticket = atomicAdd(&g_ticket, 1u);
        if (ticket == gridDim.x - 1) {
            float vals[16];
            #pragma unroll
            for (int i = 0; i < 16; ++i)
                vals[i] = atomicAdd(&g_acc[i], 0.0f);   // L2-fresh read

            const float invT = 1.0f / (float)T_TOK;
            float s = 0.0f;
            #pragma unroll
            for (int e = 0; e < N_EXP; ++e)
                s += (vals[N_EXP + e] * invT) * (vals[e] * invT);
            out[12 * T_TOK] = 0.01f * (float)N_EXP * s;

            #pragma unroll
            for (int i = 0; i < 16; ++i) g_acc[i] = 0.0f;
            g_ticket = 0u;
        }
    }
}

extern "C" void kernel_launch(void* const* d_in, const int* in_sizes, int n_in,
                              void* d_out, int out_size)
{
    const float* hidden = (const float*)d_in[0];
    const float* gate_w = (const float*)d_in[1];
    float* out = (float*)d_out;
    (void)in_sizes; (void)n_in; (void)out_size;

    const int smem = N_EXP * H_DIM * (int)sizeof(float);   // 131072 bytes
    cudaFuncSetAttribute(router_kernel,
                         cudaFuncAttributeMaxDynamicSharedMemorySize, smem);

    router_kernel<<<NBLK, 512, smem>>>(hidden, gate_w, out);
}

// round 6
// speedup vs baseline: 1.5818x; 1.1713x over previous
#include <cuda_runtime.h>
#include <cstdint>

// Problem constants (fixed-shape problem)
#define T_TOK 16384
#define H_DIM 4096
#define N_EXP 8
#define TOPK  2
#define NBLK  148
#define NWARP 32          // warps per block (1024 threads)

// Global accumulators for aux loss: [0..8) = sum of probs per expert,
// [8..16) = top1 counts. Zero-initialized at module load; the LAST block of
// each launch consumes them and resets to zero (deterministic across graph
// replays, no memset node, no second kernel).
__device__ float g_acc[16];
__device__ unsigned int g_ticket = 0;

__global__ __launch_bounds__(1024, 1)
void router_kernel(const float* __restrict__ hidden,
                   const float* __restrict__ gate_w,
                   float* __restrict__ out)
{
    extern __shared__ float sw[];     // 8 * 4096 floats = 128 KB
    __shared__ float sP[N_EXP];
    __shared__ float sF[N_EXP];

    const int tid  = threadIdx.x;
    const int warp = tid >> 5;
    const int lane = tid & 31;

    if (tid < N_EXP)            sP[tid] = 0.0f;
    else if (tid < 2 * N_EXP)   sF[tid - N_EXP] = 0.0f;

    // Stage gate_w into shared memory (coalesced float4 copy, 8 per thread)
    {
        const float4* gw4 = reinterpret_cast<const float4*>(gate_w);
        float4*       sw4 = reinterpret_cast<float4*>(sw);
        #pragma unroll
        for (int k = 0; k < (N_EXP * H_DIM) / 4 / 1024; ++k)
            sw4[k * 1024 + tid] = gw4[k * 1024 + tid];
    }
    __syncthreads();

    const float4* h4  = reinterpret_cast<const float4*>(hidden);
    const float4* sw4 = reinterpret_cast<const float4*>(sw);

    float* out_w = out;                 // [T][2] routing weights
    float* out_e = out + 2 * T_TOK;     // [T][2] expert indices (as float)
    float* out_l = out + 4 * T_TOK;     // [T][8] router logits

    // 4096 groups of 4 tokens over 4736 warps: each active warp does ONE group.
    const int g = blockIdx.x * NWARP + warp;

    if (g < T_TOK / 4) {
        const int t0 = g * 4;

        float acc[4][N_EXP];
        #pragma unroll
        for (int t = 0; t < 4; ++t)
            #pragma unroll
            for (int e = 0; e < N_EXP; ++e)
                acc[t][e] = 0.0f;

        const int hbase = t0 * (H_DIM / 4) + lane;   // float4 index

        for (int it = 0; it < H_DIM / 128; ++it) {   // 32 iterations x 128 cols
            float4 h[4];
            #pragma unroll
            for (int t = 0; t < 4; ++t)
                h[t] = __ldcs(&h4[hbase + t * (H_DIM / 4) + it * 32]);

            const int wbase = it * 32 + lane;
            #pragma unroll
            for (int e = 0; e < N_EXP; ++e) {
                const float4 w = sw4[e * (H_DIM / 4) + wbase];
                #pragma unroll
                for (int t = 0; t < 4; ++t) {
                    acc[t][e] = fmaf(h[t].x, w.x,
                                fmaf(h[t].y, w.y,
                                fmaf(h[t].z, w.z,
                                fmaf(h[t].w, w.w, acc[t][e]))));
                }
            }
        }

        // Butterfly reduction: every lane ends with the full dot products
        #pragma unroll
        for (int t = 0; t < 4; ++t)
            #pragma unroll
            for (int e = 0; e < N_EXP; ++e)
                #pragma unroll
                for (int off = 16; off > 0; off >>= 1)
                    acc[t][e] += __shfl_xor_sync(0xffffffffu, acc[t][e], off);

        // Lanes 0..3 each finish one token
        if (lane < 4) {
            const int token = t0 + lane;
            float l[N_EXP];
            #pragma unroll
            for (int e = 0; e < N_EXP; ++e) l[e] = acc[lane][e];

            float m = l[0];
            #pragma unroll
            for (int e = 1; e < N_EXP; ++e) m = fmaxf(m, l[e]);

            float p[N_EXP];
            float s = 0.0f;
            #pragma unroll
            for (int e = 0; e < N_EXP; ++e) { p[e] = __expf(l[e] - m); s += p[e]; }
            const float inv = 1.0f / s;
            #pragma unroll
            for (int e = 0; e < N_EXP; ++e) p[e] *= inv;

            int i1 = 0;
            #pragma unroll
            for (int e = 1; e < N_EXP; ++e) if (l[e] > l[i1]) i1 = e;
            int i2 = -1;
            #pragma unroll
            for (int e = 0; e < N_EXP; ++e) {
                if (e == i1) continue;
                if (i2 < 0 || l[e] > l[i2]) i2 = e;
            }

            const float w1 = p[i1], w2 = p[i2];
            const float si = 1.0f / (w1 + w2);
            out_w[token * 2 + 0] = w1 * si;
            out_w[token * 2 + 1] = w2 * si;
            out_e[token * 2 + 0] = (float)i1;
            out_e[token * 2 + 1] = (float)i2;

            reinterpret_cast<float4*>(out_l)[token * 2 + 0] =
                make_float4(l[0], l[1], l[2], l[3]);
            reinterpret_cast<float4*>(out_l)[token * 2 + 1] =
                make_float4(l[4], l[5], l[6], l[7]);

            #pragma unroll
            for (int e = 0; e < N_EXP; ++e) atomicAdd(&sP[e], p[e]);
            atomicAdd(&sF[i1], 1.0f);
        }
    }

    __syncthreads();
    if (tid < N_EXP)           atomicAdd(&g_acc[tid], sP[tid]);
    else if (tid < 2 * N_EXP)  atomicAdd(&g_acc[tid], sF[tid - N_EXP]);
    __syncthreads();

    // Last-block finalize: compute aux loss, then reset the global
    // accumulators so the next graph replay starts clean.
    if (tid == 0) {
        __threadfence();
        unsigned int ticket = atomicAdd(&g_ticket, 1u);
        if (ticket == gridDim.x - 1) {
            float vals[16];
            #pragma unroll
            for (int i = 0; i < 16; ++i)
                vals[i] = atomicAdd(&g_acc[i], 0.0f);   // L2-fresh read

            const float invT = 1.0f / (float)T_TOK;
            float s = 0.0f;
            #pragma unroll
            for (int e = 0; e < N_EXP; ++e)
                s += (vals[N_EXP + e] * invT) * (vals[e] * invT);
            out[12 * T_TOK] = 0.01f * (float)N_EXP * s;

            #pragma unroll
            for (int i = 0; i < 16; ++i) g_acc[i] = 0.0f;
            g_ticket = 0u;
        }
    }
}

extern "C" void kernel_launch(void* const* d_in, const int* in_sizes, int n_in,
                              void* d_out, int out_size)
{
    const float* hidden = (const float*)d_in[0];
    const float* gate_w = (const float*)d_in[1];
    float* out = (float*)d_out;
    (void)in_sizes; (void)n_in; (void)out_size;

    const int smem = N_EXP * H_DIM * (int)sizeof(float);   // 131072 bytes
    cudaFuncSetAttribute(router_kernel,
                         cudaFuncAttributeMaxDynamicSharedMemorySize, smem);

    router_kernel<<<NBLK, NWARP * 32, smem>>>(hidden, gate_w, out);
}